// round 1
// baseline (speedup 1.0000x reference)
#include <cuda_runtime.h>

#define EPS    1e-6f
#define MARGIN 0.5f
#define D      128

// Max blocks for the partial-sum array: T <= 262144 triplets, 8 warps/block
// -> <= 32768 blocks. Static device scratch (no allocation allowed).
#define MAX_BLOCKS 65536
static __device__ float g_partial[MAX_BLOCKS];

// One warp per triplet. Each lane loads one float4 (4 floats) of each of the
// three gathered rows -> 32 lanes x 16B = 512B per row, fully coalesced.
__global__ void __launch_bounds__(256)
triplet_partial_kernel(const float* __restrict__ emb,
                       const int*   __restrict__ a_idx,
                       const int*   __restrict__ p_idx,
                       const int*   __restrict__ n_idx,
                       int T)
{
    const int warp_in_block = threadIdx.x >> 5;
    const int lane          = threadIdx.x & 31;
    const int warp_global   = blockIdx.x * (blockDim.x >> 5) + warp_in_block;

    float loss = 0.0f;
    if (warp_global < T) {
        // Broadcast loads (all lanes same address -> single transaction)
        const int ia = a_idx[warp_global];
        const int ip = p_idx[warp_global];
        const int in = n_idx[warp_global];

        const float4* __restrict__ A = (const float4*)(emb + (size_t)ia * D);
        const float4* __restrict__ P = (const float4*)(emb + (size_t)ip * D);
        const float4* __restrict__ Nn = (const float4*)(emb + (size_t)in * D);

        // Issue all three loads before consuming -> MLP=3 per lane
        const float4 a = A[lane];
        const float4 p = P[lane];
        const float4 n = Nn[lane];

        float dp, sp = 0.0f, sn = 0.0f;
        dp = a.x - p.x + EPS; sp += dp * dp;
        dp = a.y - p.y + EPS; sp += dp * dp;
        dp = a.z - p.z + EPS; sp += dp * dp;
        dp = a.w - p.w + EPS; sp += dp * dp;

        dp = a.x - n.x + EPS; sn += dp * dp;
        dp = a.y - n.y + EPS; sn += dp * dp;
        dp = a.z - n.z + EPS; sn += dp * dp;
        dp = a.w - n.w + EPS; sn += dp * dp;

        // Warp tree reduction (fixed order -> deterministic)
        #pragma unroll
        for (int off = 16; off > 0; off >>= 1) {
            sp += __shfl_xor_sync(0xFFFFFFFFu, sp, off);
            sn += __shfl_xor_sync(0xFFFFFFFFu, sn, off);
        }

        const float d_pos = sqrtf(sp);
        const float d_neg = sqrtf(sn);
        loss = fmaxf(d_pos - d_neg + MARGIN, 0.0f);
    }

    // Block reduction over the 8 warps (lane 0 of each warp holds `loss`;
    // all lanes in a warp hold the same value, so just use lane 0's).
    __shared__ float warp_sum[8];
    if (lane == 0) warp_sum[warp_in_block] = loss;
    __syncthreads();

    if (threadIdx.x == 0) {
        float s = 0.0f;
        #pragma unroll
        for (int w = 0; w < 8; w++) s += warp_sum[w];
        g_partial[blockIdx.x] = s;
    }
}

// Deterministic final reduction over block partials, single block.
__global__ void __launch_bounds__(1024)
triplet_final_kernel(float* __restrict__ out, int nblocks, int T)
{
    __shared__ float sh[1024];
    float s = 0.0f;
    for (int i = threadIdx.x; i < nblocks; i += 1024)
        s += g_partial[i];
    sh[threadIdx.x] = s;
    __syncthreads();

    #pragma unroll
    for (int off = 512; off > 0; off >>= 1) {
        if (threadIdx.x < off) sh[threadIdx.x] += sh[threadIdx.x + off];
        __syncthreads();
    }

    if (threadIdx.x == 0)
        out[0] = sh[0] / (float)T;
}

extern "C" void kernel_launch(void* const* d_in, const int* in_sizes, int n_in,
                              void* d_out, int out_size)
{
    const float* emb   = (const float*)d_in[0];
    // d_in[1] = labels (unused; triplets are pre-mined)
    const int*   a_idx = (const int*)d_in[2];
    const int*   p_idx = (const int*)d_in[3];
    const int*   n_idx = (const int*)d_in[4];
    float*       out   = (float*)d_out;

    const int T = in_sizes[2];              // number of triplets
    const int warps_per_block = 8;          // 256 threads
    const int nblocks = (T + warps_per_block - 1) / warps_per_block;

    triplet_partial_kernel<<<nblocks, 256>>>(emb, a_idx, p_idx, n_idx, T);
    triplet_final_kernel<<<1, 1024>>>(out, nblocks, T);
}

// round 2
// speedup vs baseline: 1.2280x; 1.2280x over previous
#include <cuda_runtime.h>

#define EPS    1e-6f
#define MARGIN 0.5f
#define D      128
#define NBLOCKS 1184            // 148 SMs x 8 blocks
#define TPB     256
#define WPB     8               // warps per block
#define BATCH   4               // triplets per warp per iteration

static __device__ float g_partial[NBLOCKS];

__device__ __forceinline__ void accum_dist(const float4& a, const float4& b, float& s)
{
    float d;
    d = a.x - b.x + EPS; s += d * d;
    d = a.y - b.y + EPS; s += d * d;
    d = a.z - b.z + EPS; s += d * d;
    d = a.w - b.w + EPS; s += d * d;
}

__global__ void __launch_bounds__(TPB)
triplet_partial_kernel(const float* __restrict__ emb,
                       const int*   __restrict__ a_idx,
                       const int*   __restrict__ p_idx,
                       const int*   __restrict__ n_idx,
                       int T)
{
    const int lane  = threadIdx.x & 31;
    const int w     = threadIdx.x >> 5;
    const int gw    = blockIdx.x * WPB + w;       // global warp id
    const int nwarp = gridDim.x * WPB;

    const int Tfull = T & ~(BATCH - 1);

    float acc = 0.0f;   // identical across lanes (butterfly sums)

    // ---- batched main loop: 4 triplets per warp per iteration ----
    for (int t = gw * BATCH; t + BATCH <= Tfull + BATCH - 1 && t + BATCH <= T;
         t += nwarp * BATCH) {
        int ia[BATCH], ip[BATCH], in_[BATCH];
        #pragma unroll
        for (int k = 0; k < BATCH; k++) {
            ia[k]  = __ldg(a_idx + t + k);
            ip[k]  = __ldg(p_idx + t + k);
            in_[k] = __ldg(n_idx + t + k);
        }

        // Issue all 12 gathers before consuming -> MLP = 12 per lane
        float4 va[BATCH], vp[BATCH], vn[BATCH];
        #pragma unroll
        for (int k = 0; k < BATCH; k++) {
            va[k] = __ldg((const float4*)(emb + (size_t)ia[k]  * D) + lane);
            vp[k] = __ldg((const float4*)(emb + (size_t)ip[k]  * D) + lane);
            vn[k] = __ldg((const float4*)(emb + (size_t)in_[k] * D) + lane);
        }

        float sp[BATCH], sn[BATCH];
        #pragma unroll
        for (int k = 0; k < BATCH; k++) {
            sp[k] = 0.0f; sn[k] = 0.0f;
            accum_dist(va[k], vp[k], sp[k]);
            accum_dist(va[k], vn[k], sn[k]);
        }

        // 8 independent butterfly chains -> pipelined shfl latency
        #pragma unroll
        for (int off = 16; off > 0; off >>= 1) {
            #pragma unroll
            for (int k = 0; k < BATCH; k++) {
                sp[k] += __shfl_xor_sync(0xFFFFFFFFu, sp[k], off);
                sn[k] += __shfl_xor_sync(0xFFFFFFFFu, sn[k], off);
            }
        }

        #pragma unroll
        for (int k = 0; k < BATCH; k++)
            acc += fmaxf(sqrtf(sp[k]) - sqrtf(sn[k]) + MARGIN, 0.0f);
    }

    // ---- tail: up to BATCH-1 leftover triplets, one per warp ----
    for (int t = Tfull + gw; t < T; t += nwarp) {
        const int ia  = __ldg(a_idx + t);
        const int ip  = __ldg(p_idx + t);
        const int in_ = __ldg(n_idx + t);

        const float4 a = __ldg((const float4*)(emb + (size_t)ia  * D) + lane);
        const float4 p = __ldg((const float4*)(emb + (size_t)ip  * D) + lane);
        const float4 n = __ldg((const float4*)(emb + (size_t)in_ * D) + lane);

        float sp = 0.0f, sn = 0.0f;
        accum_dist(a, p, sp);
        accum_dist(a, n, sn);

        #pragma unroll
        for (int off = 16; off > 0; off >>= 1) {
            sp += __shfl_xor_sync(0xFFFFFFFFu, sp, off);
            sn += __shfl_xor_sync(0xFFFFFFFFu, sn, off);
        }
        acc += fmaxf(sqrtf(sp) - sqrtf(sn) + MARGIN, 0.0f);
    }

    // ---- block reduction, fixed order -> deterministic ----
    __shared__ float ws[WPB];
    if (lane == 0) ws[w] = acc;
    __syncthreads();
    if (threadIdx.x == 0) {
        float s = 0.0f;
        #pragma unroll
        for (int i = 0; i < WPB; i++) s += ws[i];
        g_partial[blockIdx.x] = s;
    }
}

// Final reduction over NBLOCKS partials (small: 1184 floats).
__global__ void __launch_bounds__(TPB)
triplet_final_kernel(float* __restrict__ out, int T)
{
    __shared__ float sh[TPB];
    float s = 0.0f;
    for (int i = threadIdx.x; i < NBLOCKS; i += TPB)
        s += g_partial[i];
    sh[threadIdx.x] = s;
    __syncthreads();

    #pragma unroll
    for (int off = TPB / 2; off > 0; off >>= 1) {
        if (threadIdx.x < off) sh[threadIdx.x] += sh[threadIdx.x + off];
        __syncthreads();
    }
    if (threadIdx.x == 0)
        out[0] = sh[0] / (float)T;
}

extern "C" void kernel_launch(void* const* d_in, const int* in_sizes, int n_in,
                              void* d_out, int out_size)
{
    const float* emb   = (const float*)d_in[0];
    const int*   a_idx = (const int*)d_in[2];
    const int*   p_idx = (const int*)d_in[3];
    const int*   n_idx = (const int*)d_in[4];
    float*       out   = (float*)d_out;

    const int T = in_sizes[2];

    triplet_partial_kernel<<<NBLOCKS, TPB>>>(emb, a_idx, p_idx, n_idx, T);
    triplet_final_kernel<<<1, TPB>>>(out, T);
}

// round 3
// speedup vs baseline: 1.2487x; 1.0168x over previous
#include <cuda_runtime.h>

#define EPS    1e-6f
#define MARGIN 0.5f
#define D      128
#define NBLOCKS 1184            // 148 SMs x 8 blocks
#define TPB     256
#define WPB     8               // warps per block
#define BATCH   4               // triplets per warp per iteration

static __device__ float        g_partial[NBLOCKS];
static __device__ unsigned int g_ticket;   // zero-initialized; reset by last block

__device__ __forceinline__ void accum_dist(const float4& a, const float4& b, float& s)
{
    float d;
    d = a.x - b.x + EPS; s += d * d;
    d = a.y - b.y + EPS; s += d * d;
    d = a.z - b.z + EPS; s += d * d;
    d = a.w - b.w + EPS; s += d * d;
}

__global__ void __launch_bounds__(TPB)
triplet_kernel(const float* __restrict__ emb,
               const int*   __restrict__ a_idx,
               const int*   __restrict__ p_idx,
               const int*   __restrict__ n_idx,
               float* __restrict__ out,
               int T)
{
    const int lane  = threadIdx.x & 31;
    const int w     = threadIdx.x >> 5;
    const int gw    = blockIdx.x * WPB + w;       // global warp id
    const int nwarp = gridDim.x * WPB;

    const int Tfull = T & ~(BATCH - 1);

    float acc = 0.0f;   // identical across lanes (butterfly sums)

    // ---- batched main loop: 4 triplets per warp per iteration ----
    for (int t = gw * BATCH; t + BATCH <= Tfull; t += nwarp * BATCH) {
        int ia[BATCH], ip[BATCH], in_[BATCH];
        #pragma unroll
        for (int k = 0; k < BATCH; k++) {
            ia[k]  = __ldg(a_idx + t + k);
            ip[k]  = __ldg(p_idx + t + k);
            in_[k] = __ldg(n_idx + t + k);
        }

        // Issue all 12 gathers before consuming -> MLP = 12 per lane
        float4 va[BATCH], vp[BATCH], vn[BATCH];
        #pragma unroll
        for (int k = 0; k < BATCH; k++) {
            va[k] = __ldg((const float4*)(emb + (size_t)ia[k]  * D) + lane);
            vp[k] = __ldg((const float4*)(emb + (size_t)ip[k]  * D) + lane);
            vn[k] = __ldg((const float4*)(emb + (size_t)in_[k] * D) + lane);
        }

        float sp[BATCH], sn[BATCH];
        #pragma unroll
        for (int k = 0; k < BATCH; k++) {
            sp[k] = 0.0f; sn[k] = 0.0f;
            accum_dist(va[k], vp[k], sp[k]);
            accum_dist(va[k], vn[k], sn[k]);
        }

        // 8 independent butterfly chains -> pipelined shfl latency
        #pragma unroll
        for (int off = 16; off > 0; off >>= 1) {
            #pragma unroll
            for (int k = 0; k < BATCH; k++) {
                sp[k] += __shfl_xor_sync(0xFFFFFFFFu, sp[k], off);
                sn[k] += __shfl_xor_sync(0xFFFFFFFFu, sn[k], off);
            }
        }

        #pragma unroll
        for (int k = 0; k < BATCH; k++)
            acc += fmaxf(sqrtf(sp[k]) - sqrtf(sn[k]) + MARGIN, 0.0f);
    }

    // ---- tail: leftover triplets, one per warp ----
    for (int t = Tfull + gw; t < T; t += nwarp) {
        const int ia  = __ldg(a_idx + t);
        const int ip  = __ldg(p_idx + t);
        const int in_ = __ldg(n_idx + t);

        const float4 a = __ldg((const float4*)(emb + (size_t)ia  * D) + lane);
        const float4 p = __ldg((const float4*)(emb + (size_t)ip  * D) + lane);
        const float4 n = __ldg((const float4*)(emb + (size_t)in_ * D) + lane);

        float sp = 0.0f, sn = 0.0f;
        accum_dist(a, p, sp);
        accum_dist(a, n, sn);

        #pragma unroll
        for (int off = 16; off > 0; off >>= 1) {
            sp += __shfl_xor_sync(0xFFFFFFFFu, sp, off);
            sn += __shfl_xor_sync(0xFFFFFFFFu, sn, off);
        }
        acc += fmaxf(sqrtf(sp) - sqrtf(sn) + MARGIN, 0.0f);
    }

    // ---- block reduction, fixed order -> deterministic ----
    __shared__ float ws[WPB];
    __shared__ bool  is_last;
    if (lane == 0) ws[w] = acc;
    __syncthreads();
    if (threadIdx.x == 0) {
        float s = 0.0f;
        #pragma unroll
        for (int i = 0; i < WPB; i++) s += ws[i];
        g_partial[blockIdx.x] = s;
        __threadfence();
        unsigned int done = atomicAdd(&g_ticket, 1u);
        is_last = (done == (unsigned)(gridDim.x - 1));
    }
    __syncthreads();

    // ---- last block folds all partials: deterministic fixed-order tree ----
    if (is_last) {
        __shared__ float sh[TPB];
        float s = 0.0f;
        for (int i = threadIdx.x; i < NBLOCKS; i += TPB)
            s += g_partial[i];
        sh[threadIdx.x] = s;
        __syncthreads();
        #pragma unroll
        for (int off = TPB / 2; off > 0; off >>= 1) {
            if (threadIdx.x < off) sh[threadIdx.x] += sh[threadIdx.x + off];
            __syncthreads();
        }
        if (threadIdx.x == 0) {
            out[0] = sh[0] / (float)T;
            g_ticket = 0;          // reset for next graph replay
        }
    }
}

extern "C" void kernel_launch(void* const* d_in, const int* in_sizes, int n_in,
                              void* d_out, int out_size)
{
    const float* emb   = (const float*)d_in[0];
    const int*   a_idx = (const int*)d_in[2];
    const int*   p_idx = (const int*)d_in[3];
    const int*   n_idx = (const int*)d_in[4];
    float*       out   = (float*)d_out;

    const int T = in_sizes[2];

    triplet_kernel<<<NBLOCKS, TPB>>>(emb, a_idx, p_idx, n_idx, out, T);
}

// round 4
// speedup vs baseline: 1.4002x; 1.1213x over previous
#include <cuda_runtime.h>

#define EPS    1e-6f
#define MARGIN 0.5f
#define D      128
#define TPB    128
#define WPB    4               // warps per block
#define BATCH  4               // triplets per warp per iteration
#define MAXBLK 4096

static __device__ float        g_partial[MAXBLK];
static __device__ unsigned int g_ticket;   // zero-init; reset by last block each run

__device__ __forceinline__ float fsqrt_approx(float x)
{
    float r;
    asm("sqrt.approx.f32 %0, %1;" : "=f"(r) : "f"(x));
    return r;
}

struct BatchData {
    float4 a[BATCH], p[BATCH], n[BATCH];
    float  valid[BATCH];
};

__device__ __forceinline__ void load_batch(const float* __restrict__ emb,
                                           const int* __restrict__ ai,
                                           const int* __restrict__ pi,
                                           const int* __restrict__ ni,
                                           int t, int T, int lane, BatchData& B)
{
    #pragma unroll
    for (int k = 0; k < BATCH; k++) {
        const int  tt = t + k;
        const bool v  = (tt < T);
        const int  ix = v ? tt : 0;
        const int ia = __ldg(ai + ix);
        const int ip = __ldg(pi + ix);
        const int in = __ldg(ni + ix);
        B.a[k] = __ldg((const float4*)(emb + (size_t)ia * D) + lane);
        B.p[k] = __ldg((const float4*)(emb + (size_t)ip * D) + lane);
        B.n[k] = __ldg((const float4*)(emb + (size_t)in * D) + lane);
        B.valid[k] = v ? 1.0f : 0.0f;
    }
}

__device__ __forceinline__ void accum_dist(const float4& a, const float4& b, float& s)
{
    float d;
    d = a.x - b.x + EPS; s += d * d;
    d = a.y - b.y + EPS; s += d * d;
    d = a.z - b.z + EPS; s += d * d;
    d = a.w - b.w + EPS; s += d * d;
}

__device__ __forceinline__ float compute_batch(const BatchData& B)
{
    float sp[BATCH], sn[BATCH];
    #pragma unroll
    for (int k = 0; k < BATCH; k++) {
        sp[k] = 0.0f; sn[k] = 0.0f;
        accum_dist(B.a[k], B.p[k], sp[k]);
        accum_dist(B.a[k], B.n[k], sn[k]);
    }
    // 8 independent butterfly chains, pipelined across SHFL latency
    #pragma unroll
    for (int off = 16; off > 0; off >>= 1) {
        #pragma unroll
        for (int k = 0; k < BATCH; k++) {
            sp[k] += __shfl_xor_sync(0xFFFFFFFFu, sp[k], off);
            sn[k] += __shfl_xor_sync(0xFFFFFFFFu, sn[k], off);
        }
    }
    float acc = 0.0f;
    #pragma unroll
    for (int k = 0; k < BATCH; k++) {
        const float l = fsqrt_approx(sp[k]) - fsqrt_approx(sn[k]) + MARGIN;
        acc += B.valid[k] * fmaxf(l, 0.0f);
    }
    return acc;
}

__global__ void __launch_bounds__(TPB, 3)
triplet_kernel(const float* __restrict__ emb,
               const int*   __restrict__ a_idx,
               const int*   __restrict__ p_idx,
               const int*   __restrict__ n_idx,
               float* __restrict__ out,
               int T, int nblocks)
{
    const int lane   = threadIdx.x & 31;
    const int w      = threadIdx.x >> 5;
    const int gw     = blockIdx.x * WPB + w;
    const int nwarp  = nblocks * WPB;
    const int stride = nwarp * BATCH;

    float acc = 0.0f;

    int t = gw * BATCH;
    if (t < T) {
        BatchData A, B;
        load_batch(emb, a_idx, p_idx, n_idx, t, T, lane, A);
        // Software pipeline: issue next batch's gathers before reducing current.
        for (; t < T; t += stride) {
            const int tn = t + stride;
            if (tn < T)
                load_batch(emb, a_idx, p_idx, n_idx, tn, T, lane, B);
            acc += compute_batch(A);
            A = B;
        }
    }

    // ---- block reduction, fixed order -> deterministic ----
    __shared__ float ws[WPB];
    __shared__ bool  is_last;
    if (lane == 0) ws[w] = acc;
    __syncthreads();
    if (threadIdx.x == 0) {
        float s = 0.0f;
        #pragma unroll
        for (int i = 0; i < WPB; i++) s += ws[i];
        g_partial[blockIdx.x] = s;
        __threadfence();
        unsigned int done = atomicAdd(&g_ticket, 1u);
        is_last = (done == (unsigned)(nblocks - 1));
    }
    __syncthreads();

    // ---- last block folds all partials: deterministic fixed-order tree ----
    if (is_last) {
        __shared__ float sh[TPB];
        float s = 0.0f;
        for (int i = threadIdx.x; i < nblocks; i += TPB)
            s += g_partial[i];
        sh[threadIdx.x] = s;
        __syncthreads();
        #pragma unroll
        for (int off = TPB / 2; off > 0; off >>= 1) {
            if (threadIdx.x < off) sh[threadIdx.x] += sh[threadIdx.x + off];
            __syncthreads();
        }
        if (threadIdx.x == 0) {
            out[0] = sh[0] / (float)T;
            g_ticket = 0;          // reset for next graph replay
        }
    }
}

extern "C" void kernel_launch(void* const* d_in, const int* in_sizes, int n_in,
                              void* d_out, int out_size)
{
    const float* emb   = (const float*)d_in[0];
    const int*   a_idx = (const int*)d_in[2];
    const int*   p_idx = (const int*)d_in[3];
    const int*   n_idx = (const int*)d_in[4];
    float*       out   = (float*)d_out;

    const int T = in_sizes[2];

    // Occupancy-exact persistent grid: no straggler waves.
    int dev = 0, nsm = 148, bpm = 3;
    cudaGetDevice(&dev);
    cudaDeviceGetAttribute(&nsm, cudaDevAttrMultiProcessorCount, dev);
    cudaOccupancyMaxActiveBlocksPerMultiprocessor(&bpm, triplet_kernel, TPB, 0);
    if (bpm < 1) bpm = 1;
    int nblocks = nsm * bpm;
    if (nblocks > MAXBLK) nblocks = MAXBLK;

    triplet_kernel<<<nblocks, TPB>>>(emb, a_idx, p_idx, n_idx, out, T, nblocks);
}

// round 5
// speedup vs baseline: 1.4347x; 1.0247x over previous
#include <cuda_runtime.h>

#define EPS    1e-6f
#define MARGIN 0.5f
#define D      128
#define TPB    128
#define WPB    4               // warps per block
#define BATCH  4               // triplets per warp per iteration
#define MAXBLK 4096

static __device__ float        g_partial[MAXBLK];
static __device__ unsigned int g_ticket;

__device__ __forceinline__ float fsqrt_approx(float x)
{
    float r;
    asm("sqrt.approx.f32 %0, %1;" : "=f"(r) : "f"(x));
    return r;
}

struct BatchData {
    float4 a[BATCH], p[BATCH], n[BATCH];
};

__device__ __forceinline__ void load_batch(const float* __restrict__ emb,
                                           const int* __restrict__ ai,
                                           const int* __restrict__ pi,
                                           const int* __restrict__ ni,
                                           int t, int T, int lane, BatchData& B)
{
    #pragma unroll
    for (int k = 0; k < BATCH; k++) {
        const int ix = (t + k < T) ? (t + k) : 0;
        const int ia = __ldg(ai + ix);
        const int ip = __ldg(pi + ix);
        const int in = __ldg(ni + ix);
        B.a[k] = __ldg((const float4*)(emb + (size_t)ia * D) + lane);
        B.p[k] = __ldg((const float4*)(emb + (size_t)ip * D) + lane);
        B.n[k] = __ldg((const float4*)(emb + (size_t)in * D) + lane);
    }
}

__device__ __forceinline__ void accum_dist(const float4& a, const float4& b, float& s)
{
    float d;
    d = a.x - b.x + EPS; s += d * d;
    d = a.y - b.y + EPS; s += d * d;
    d = a.z - b.z + EPS; s += d * d;
    d = a.w - b.w + EPS; s += d * d;
}

// Multi-value folding butterfly: reduces 8 per-lane partials (sp0..3, sn0..3)
// across the warp in 16 SHFLs. Afterward every lane holds ONE complete sum:
//   kind = (lane>>4)&1  (0 = sp, 1 = sn)
//   trip = ((lane>>3)&1)*2 + ((lane>>2)&1)
// Returns this lane's contribution to the loss accumulator (non-uniform).
__device__ __forceinline__ float compute_batch(const BatchData& B, int t, int T, int lane)
{
    float v[8];
    #pragma unroll
    for (int k = 0; k < BATCH; k++) {
        float sp = 0.0f, sn = 0.0f;
        accum_dist(B.a[k], B.p[k], sp);
        accum_dist(B.a[k], B.n[k], sn);
        v[k] = sp; v[k + 4] = sn;
    }

    const unsigned FULL = 0xFFFFFFFFu;
    // off=16: fold sp_k with sn_k (8 shfl)
    float w[4];
    #pragma unroll
    for (int k = 0; k < 4; k++) {
        float a  = v[k], b = v[k + 4];
        float a2 = __shfl_xor_sync(FULL, a, 16);
        float b2 = __shfl_xor_sync(FULL, b, 16);
        w[k] = (lane & 16) ? (b + b2) : (a + a2);
    }
    // off=8: fold k with k+2 (4 shfl)
    float x[2];
    #pragma unroll
    for (int k = 0; k < 2; k++) {
        float a  = w[k], b = w[k + 2];
        float a2 = __shfl_xor_sync(FULL, a, 8);
        float b2 = __shfl_xor_sync(FULL, b, 8);
        x[k] = (lane & 8) ? (b + b2) : (a + a2);
    }
    // off=4: fold x0 with x1 (2 shfl)
    {
        float a  = x[0], b = x[1];
        float a2 = __shfl_xor_sync(FULL, a, 4);
        float b2 = __shfl_xor_sync(FULL, b, 4);
        x[0] = (lane & 4) ? (b + b2) : (a + a2);
    }
    // off=2,1: plain butterfly (2 shfl)
    x[0] += __shfl_xor_sync(FULL, x[0], 2);
    x[0] += __shfl_xor_sync(FULL, x[0], 1);

    // One sqrt instruction per warp covers all 8 sums.
    const float r  = fsqrt_approx(x[0]);
    const float rn = __shfl_xor_sync(FULL, r, 16);   // partner kind's sqrt

    const int  trip  = (((lane >> 3) & 1) << 1) | ((lane >> 2) & 1);
    const bool kind0 = (lane & 16) == 0;
    const bool valid = (t + trip) < T;

    // Each triplet's loss is produced by 4 duplicate kind0 lanes -> scaled by
    // 0.25 at the end (in the caller's final warp reduction).
    float loss = fmaxf(r - rn + MARGIN, 0.0f);
    return (kind0 && valid) ? loss : 0.0f;
}

__global__ void __launch_bounds__(TPB, 4)
triplet_kernel(const float* __restrict__ emb,
               const int*   __restrict__ a_idx,
               const int*   __restrict__ p_idx,
               const int*   __restrict__ n_idx,
               float* __restrict__ out,
               int T, int nblocks)
{
    const int lane   = threadIdx.x & 31;
    const int w      = threadIdx.x >> 5;
    const int gw     = blockIdx.x * WPB + w;
    const int stride = nblocks * WPB * BATCH;

    float acc = 0.0f;   // per-lane (non-uniform) accumulator

    int t = gw * BATCH;
    if (t < T) {
        BatchData A, B;
        load_batch(emb, a_idx, p_idx, n_idx, t, T, lane, A);
        // 2x-unrolled ping-pong software pipeline (no struct copies).
        while (true) {
            const int t2 = t + stride;
            if (t2 < T) load_batch(emb, a_idx, p_idx, n_idx, t2, T, lane, B);
            acc += compute_batch(A, t, T, lane);
            if (t2 >= T) break;

            const int t3 = t2 + stride;
            if (t3 < T) load_batch(emb, a_idx, p_idx, n_idx, t3, T, lane, A);
            acc += compute_batch(B, t2, T, lane);
            if (t3 >= T) break;
            t = t3;
        }
    }

    // Final per-warp reduction of the non-uniform accumulator (once per warp).
    const unsigned FULL = 0xFFFFFFFFu;
    #pragma unroll
    for (int off = 16; off > 0; off >>= 1)
        acc += __shfl_xor_sync(FULL, acc, off);
    acc *= 0.25f;   // 4 duplicate lanes contributed each triplet

    // ---- block reduction, fixed order -> deterministic ----
    __shared__ float ws[WPB];
    __shared__ bool  is_last;
    if (lane == 0) ws[w] = acc;
    __syncthreads();
    if (threadIdx.x == 0) {
        float s = 0.0f;
        #pragma unroll
        for (int i = 0; i < WPB; i++) s += ws[i];
        g_partial[blockIdx.x] = s;
        __threadfence();
        unsigned int done = atomicAdd(&g_ticket, 1u);
        is_last = (done == (unsigned)(nblocks - 1));
    }
    __syncthreads();

    // ---- last block folds all partials: deterministic fixed-order tree ----
    if (is_last) {
        __shared__ float sh[TPB];
        float s = 0.0f;
        for (int i = threadIdx.x; i < nblocks; i += TPB)
            s += g_partial[i];
        sh[threadIdx.x] = s;
        __syncthreads();
        #pragma unroll
        for (int off = TPB / 2; off > 0; off >>= 1) {
            if (threadIdx.x < off) sh[threadIdx.x] += sh[threadIdx.x + off];
            __syncthreads();
        }
        if (threadIdx.x == 0) {
            out[0] = sh[0] / (float)T;
            g_ticket = 0;          // reset for next graph replay
        }
    }
}

extern "C" void kernel_launch(void* const* d_in, const int* in_sizes, int n_in,
                              void* d_out, int out_size)
{
    const float* emb   = (const float*)d_in[0];
    const int*   a_idx = (const int*)d_in[2];
    const int*   p_idx = (const int*)d_in[3];
    const int*   n_idx = (const int*)d_in[4];
    float*       out   = (float*)d_out;

    const int T = in_sizes[2];

    int dev = 0, nsm = 148, bpm = 4;
    cudaGetDevice(&dev);
    cudaDeviceGetAttribute(&nsm, cudaDevAttrMultiProcessorCount, dev);
    cudaOccupancyMaxActiveBlocksPerMultiprocessor(&bpm, triplet_kernel, TPB, 0);
    if (bpm < 1) bpm = 1;
    int nblocks = nsm * bpm;
    if (nblocks > MAXBLK) nblocks = MAXBLK;

    triplet_kernel<<<nblocks, TPB>>>(emb, a_idx, p_idx, n_idx, out, T, nblocks);
}